// round 2
// baseline (speedup 1.0000x reference)
#include <cuda_runtime.h>

#define NN 32
#define CC 64
#define OO 64
#define TT 512
#define VV 25
#define SS 3
#define RR 32
#define EPSV 1e-5f
#define TB 8            // t-tile per block
#define NTB (TT/TB)     // 64 t-blocks
#define TVW (TB*VV)     // 200 tv elements per tile
#define VPAD 28         // padded v-row (multiple of 4 for LDS.128)
#define OROW (TB*VPAD)  // 224 floats per o in vsAll

// ---- scratch (static __device__; no allocations allowed) ----
__device__ float g_xm[NN*CC*VV];
__device__ float g_att[NN*SS*OO*VV*VV];
__device__ float g_ybias[NN*OO*VV];
__device__ float g_w3t[SS*CC*OO];                // w3 transposed: [s][c][o]
__device__ float g_y[NN*OO*TT*VV];
__device__ float g_sum[OO];
__device__ float g_sumsq[OO];
__device__ float g_scale[OO];
__device__ float g_shift[OO];

// ---- f32x2 helpers (sm_10x packed fp32) ----
typedef unsigned long long ull;
__device__ __forceinline__ ull pk2(float a, float b) {
    ull r; asm("mov.b64 %0, {%1, %2};" : "=l"(r) : "f"(a), "f"(b)); return r;
}
__device__ __forceinline__ void upk2(ull p, float& a, float& b) {
    asm("mov.b64 {%0, %1}, %2;" : "=f"(a), "=f"(b) : "l"(p));
}
__device__ __forceinline__ ull fma2(ull a, ull b, ull c) {
    ull d; asm("fma.rn.f32x2 %0, %1, %2, %3;" : "=l"(d) : "l"(a), "l"(b), "l"(c)); return d;
}

// ---------------------------------------------------------------------------
// Kernel 0: transpose w3 -> w3T[s][c][o]
// ---------------------------------------------------------------------------
__global__ void k_w3t(const float* __restrict__ w3) {
    int i = blockIdx.x * blockDim.x + threadIdx.x;
    if (i >= SS*CC*OO) return;
    int o = i % OO, c = (i / OO) % CC, s = i / (OO*CC);
    g_w3t[i] = w3[(s*OO + o)*CC + c];
}

// ---------------------------------------------------------------------------
// Kernel 1: xm[n,c,v] = mean_t x[n,c,t,v]
// ---------------------------------------------------------------------------
__global__ void k_xm(const float* __restrict__ x) {
    int idx = blockIdx.x * blockDim.x + threadIdx.x;
    if (idx >= NN*CC*VV) return;
    int v  = idx % VV;
    int nc = idx / VV;
    const float* p = x + (size_t)nc * (TT*VV) + v;
    float a0=0.f, a1=0.f, a2=0.f, a3=0.f;
    #pragma unroll 4
    for (int t = 0; t < TT; t += 4) {
        a0 += p[(t+0)*VV]; a1 += p[(t+1)*VV];
        a2 += p[(t+2)*VV]; a3 += p[(t+3)*VV];
    }
    g_xm[idx] = (a0+a1+a2+a3) * (1.0f/(float)TT);
}

// ---------------------------------------------------------------------------
// Kernel 2: attention tensor (unchanged from round 1)
// ---------------------------------------------------------------------------
__global__ void k_att(const float* __restrict__ w1, const float* __restrict__ b1,
                      const float* __restrict__ w2, const float* __restrict__ b2,
                      const float* __restrict__ w4, const float* __restrict__ b4,
                      const float* __restrict__ alpha, const float* __restrict__ A) {
    int n = blockIdx.x / SS, s = blockIdx.x % SS;
    __shared__ float xm_sm[CC*VV];
    __shared__ float q_sm[RR*VV];
    __shared__ float k_sm[RR*VV];
    __shared__ float w4_sm[OO*RR];
    __shared__ float b4_sm[OO];
    int tid = threadIdx.x;

    for (int i = tid; i < CC*VV; i += blockDim.x) xm_sm[i] = g_xm[n*CC*VV + i];
    for (int i = tid; i < OO*RR; i += blockDim.x) w4_sm[i] = w4[s*OO*RR + i];
    if (tid < OO) b4_sm[tid] = b4[s*OO + tid];
    __syncthreads();

    for (int e = tid; e < RR*VV; e += blockDim.x) {
        int r = e / VV, v = e % VV;
        const float* w1r = w1 + (s*RR + r)*CC;
        const float* w2r = w2 + (s*RR + r)*CC;
        float accq = b1[s*RR + r], acck = b2[s*RR + r];
        #pragma unroll 8
        for (int c = 0; c < CC; c++) {
            float xv = xm_sm[c*VV + v];
            accq = fmaf(w1r[c], xv, accq);
            acck = fmaf(w2r[c], xv, acck);
        }
        q_sm[e] = accq; k_sm[e] = acck;
    }
    __syncthreads();

    float al = alpha[s];
    for (int uv = tid; uv < VV*VV; uv += blockDim.x) {
        int u = uv / VV, v = uv % VV;
        float rel[RR];
        #pragma unroll
        for (int r = 0; r < RR; r++)
            rel[r] = fmaxf(q_sm[r*VV + u] - k_sm[r*VV + v], 0.f);
        float Auv = A[(s*VV + u)*VV + v];
        float* outp = g_att + (size_t)((n*SS + s)*OO) * (VV*VV) + uv;
        for (int o = 0; o < OO; o++) {
            float acc = 0.f;
            #pragma unroll
            for (int r = 0; r < RR; r++)
                acc = fmaf(w4_sm[o*RR + r], rel[r], acc);
            outp[o*VV*VV] = al*(acc + b4_sm[o]) + Auv;
        }
    }
}

// ---------------------------------------------------------------------------
// Kernel 3: ybias + zero BN stats (unchanged)
// ---------------------------------------------------------------------------
__global__ void k_ybias(const float* __restrict__ b3) {
    int n = blockIdx.x;
    int tid = threadIdx.x;
    if (n == 0) {
        if (tid < OO)             g_sum[tid] = 0.f;
        else if (tid < 2*OO)      g_sumsq[tid - OO] = 0.f;
    }
    for (int e = tid; e < OO*VV; e += blockDim.x) {
        int o = e / VV, u = e % VV;
        float acc = 0.f;
        #pragma unroll
        for (int s = 0; s < SS; s++) {
            const float* ap = g_att + (size_t)(((n*SS + s)*OO + o)*VV + u) * VV;
            float rs = 0.f;
            #pragma unroll
            for (int v = 0; v < VV; v++) rs += ap[v];
            acc = fmaf(b3[s*OO + o], rs, acc);
        }
        g_ybias[n*OO*VV + e] = acc;
    }
}

// ---------------------------------------------------------------------------
// Kernel 4 (main, rewritten): fused v = w3@x and y += att@v per (n, t-tile).
// 512 threads = 16 warps.
// v-stage: warp = (o-octet q = w&7) x (tv-half h = w>>3); f32x2 packs o-pairs.
// y-stage: warp owns o = 4w..4w+3; lane = (tp = lane>>3: t-pair, ug = lane&7:
//          u-quad); f32x2 dot-product over padded v with LDS.128 loads.
// smem: xs[64][200] | vsAll[64][8][28] | attw[16 warps][704]
// ---------------------------------------------------------------------------
#define SM_XS_F   (CC*TVW)           // 12800
#define SM_VS_F   (OO*OROW)          // 14336
#define SM_AT_F   (16*704)           // 11264
#define SMEM_FLOATS (SM_XS_F + SM_VS_F + SM_AT_F)   // 38400 = 153,600 B

__global__ void __launch_bounds__(512, 1)
k_main(const float* __restrict__ x) {
    extern __shared__ float sm[];
    float* xs    = sm;
    float* vsAll = sm + SM_XS_F;
    float* atts  = sm + SM_XS_F + SM_VS_F;

    int n  = blockIdx.x / NTB;
    int tb = blockIdx.x % NTB;
    int t0 = tb * TB;
    int tid = threadIdx.x, w = tid >> 5, lane = tid & 31;

    // --- stage x tile: [c][200] ---
    float4* xs4 = (float4*)xs;
    for (int i = tid; i < CC*50; i += 512) {
        int c = i / 50, qd = i % 50;
        xs4[c*50 + qd] = *(const float4*)(x + (size_t)(n*CC + c)*(TT*VV) + t0*VV + qd*4);
    }
    // --- zero v-row pads [25..27] (written once; dumps never touch them) ---
    for (int i = tid; i < OO*TB; i += 512) {
        float* p = vsAll + i*VPAD + VV;
        p[0] = 0.f; p[1] = 0.f; p[2] = 0.f;
    }

    // v-stage lane constants
    int q = w & 7, h = w >> 3;
    int tvt[4], tvv[4]; bool jv[4];
    #pragma unroll
    for (int j = 0; j < 4; j++) {
        int l = lane + 32*j;
        jv[j] = (l < 100);
        int tvl = jv[j] ? (100*h + l) : 0;
        tvt[j] = tvl / VV; tvv[j] = tvl % VV;
    }
    // y-stage lane constants
    int tp = lane >> 3, ug = lane & 7;
    int uoff[4];
    #pragma unroll
    for (int i = 0; i < 4; i++) {
        int u = 4*ug + i;
        uoff[i] = (u < VV ? u : (VV-1)) * VPAD;   // clamp keeps reads in attw
    }

    // y accumulators (scalar), init with ybias
    float acc2[4][2][4];
    #pragma unroll
    for (int oq = 0; oq < 4; oq++)
        #pragma unroll
        for (int i = 0; i < 4; i++) {
            int u = 4*ug + i;
            float yb = (u < VV) ? g_ybias[(n*OO + 4*w + oq)*VV + u] : 0.f;
            acc2[oq][0][i] = yb; acc2[oq][1][i] = yb;
        }

    __syncthreads();

    float* aw = atts + w*704;

    for (int s = 0; s < SS; s++) {
        // ---- v-stage: acc[opair][j] (f32x2 over o-pair) for tv = 100h+lane+32j
        ull acc[4][4];
        #pragma unroll
        for (int p = 0; p < 4; p++)
            #pragma unroll
            for (int j = 0; j < 4; j++) acc[p][j] = 0ull;

        const float* wbase = g_w3t + (size_t)(s*CC)*OO + 8*q;
        const float* xb = xs + 100*h + lane;
        #pragma unroll 4
        for (int c = 0; c < CC; c++) {
            ulonglong2 wA = *(const ulonglong2*)(wbase + c*OO);      // (o0,o1),(o2,o3)
            ulonglong2 wB = *(const ulonglong2*)(wbase + c*OO + 4);  // (o4,o5),(o6,o7)
            const float* xr = xb + c*TVW;
            ull xv[4];
            #pragma unroll
            for (int j = 0; j < 4; j++) { float xf = xr[32*j]; xv[j] = pk2(xf, xf); }
            #pragma unroll
            for (int j = 0; j < 4; j++) {
                acc[0][j] = fma2(wA.x, xv[j], acc[0][j]);
                acc[1][j] = fma2(wA.y, xv[j], acc[1][j]);
                acc[2][j] = fma2(wB.x, xv[j], acc[2][j]);
                acc[3][j] = fma2(wB.y, xv[j], acc[3][j]);
            }
        }

        __syncthreads();   // previous y-stage reads of vsAll complete

        // ---- dump vw into vsAll[o][t][28] ----
        #pragma unroll
        for (int p = 0; p < 4; p++) {
            float* d0 = vsAll + (8*q + 2*p) * OROW;
            float* d1 = d0 + OROW;
            #pragma unroll
            for (int j = 0; j < 4; j++) {
                if (jv[j]) {
                    float lo, hi; upk2(acc[p][j], lo, hi);
                    int off = tvt[j]*VPAD + tvv[j];
                    d0[off] = lo; d1[off] = hi;
                }
            }
        }
        __syncthreads();

        // ---- y-stage: o = 4w + oq ----
        #pragma unroll
        for (int oq = 0; oq < 4; oq++) {
            int o = 4*w + oq;
            // stage att[o] into padded per-warp buffer [u][28]
            const float* ag = g_att + (size_t)((n*SS + s)*OO + o) * (VV*VV);
            __syncwarp();
            for (int i = lane; i < VV*VV; i += 32)
                aw[(i/VV)*VPAD + (i%VV)] = ag[i];
            __syncwarp();

            const float* vrow = vsAll + o*OROW;
            ull accv[4][2];
            #pragma unroll
            for (int i = 0; i < 4; i++) { accv[i][0] = 0ull; accv[i][1] = 0ull; }

            #pragma unroll
            for (int vq = 0; vq < 7; vq++) {
                ulonglong2 vwa = *(const ulonglong2*)(vrow + (2*tp)*VPAD   + 4*vq);
                ulonglong2 vwb = *(const ulonglong2*)(vrow + (2*tp+1)*VPAD + 4*vq);
                #pragma unroll
                for (int i = 0; i < 4; i++) {
                    ulonglong2 at = *(const ulonglong2*)(aw + uoff[i] + 4*vq);
                    accv[i][0] = fma2(at.x, vwa.x, accv[i][0]);
                    accv[i][0] = fma2(at.y, vwa.y, accv[i][0]);
                    accv[i][1] = fma2(at.x, vwb.x, accv[i][1]);
                    accv[i][1] = fma2(at.y, vwb.y, accv[i][1]);
                }
            }
            #pragma unroll
            for (int i = 0; i < 4; i++) {
                float l0, h0, l1, h1;
                upk2(accv[i][0], l0, h0);
                upk2(accv[i][1], l1, h1);
                acc2[oq][0][i] += l0 + h0;
                acc2[oq][1][i] += l1 + h1;
            }
        }
    }

    // ---- epilogue: write y, accumulate BN stats ----
    #pragma unroll
    for (int oq = 0; oq < 4; oq++) {
        int o = 4*w + oq;
        float ps = 0.f, pss = 0.f;
        #pragma unroll
        for (int j = 0; j < 2; j++) {
            int t = 2*tp + j;
            #pragma unroll
            for (int i = 0; i < 4; i++) {
                int u = 4*ug + i;
                if (u < VV) {
                    float val = acc2[oq][j][i];
                    g_y[((size_t)(n*OO + o)*TT + t0 + t)*VV + u] = val;
                    ps  += val;
                    pss += val*val;
                }
            }
        }
        #pragma unroll
        for (int off = 16; off > 0; off >>= 1) {
            ps  += __shfl_xor_sync(0xffffffffu, ps,  off);
            pss += __shfl_xor_sync(0xffffffffu, pss, off);
        }
        if (lane == 0) {
            atomicAdd(&g_sum[o],   ps);
            atomicAdd(&g_sumsq[o], pss);
        }
    }
}

// ---------------------------------------------------------------------------
// Kernel 5: BN scale/shift
// ---------------------------------------------------------------------------
__global__ void k_bnp(const float* __restrict__ gamma, const float* __restrict__ beta) {
    int o = threadIdx.x;
    if (o < OO) {
        float cnt = (float)(NN*TT*VV);
        float mu  = g_sum[o] / cnt;
        float var = g_sumsq[o] / cnt - mu*mu;
        float sc  = gamma[o] * rsqrtf(var + EPSV);
        g_scale[o] = sc;
        g_shift[o] = beta[o] - mu*sc;
    }
}

// ---------------------------------------------------------------------------
// Kernel 6: out = relu(y) + y*scale + shift + x
// ---------------------------------------------------------------------------
__global__ void k_final(const float* __restrict__ x, float* __restrict__ out) {
    const int total4 = NN*OO*TT*VV / 4;
    for (int i = blockIdx.x*blockDim.x + threadIdx.x; i < total4; i += gridDim.x*blockDim.x) {
        int c = (i / (TT*VV/4)) % OO;
        float sc = g_scale[c], sh = g_shift[c];
        float4 y4 = ((const float4*)g_y)[i];
        float4 x4 = ((const float4*)x)[i];
        float4 r;
        r.x = fmaxf(y4.x, 0.f) + fmaf(y4.x, sc, sh) + x4.x;
        r.y = fmaxf(y4.y, 0.f) + fmaf(y4.y, sc, sh) + x4.y;
        r.z = fmaxf(y4.z, 0.f) + fmaf(y4.z, sc, sh) + x4.z;
        r.w = fmaxf(y4.w, 0.f) + fmaf(y4.w, sc, sh) + x4.w;
        ((float4*)out)[i] = r;
    }
}

// ---------------------------------------------------------------------------
extern "C" void kernel_launch(void* const* d_in, const int* in_sizes, int n_in,
                              void* d_out, int out_size) {
    (void)in_sizes; (void)n_in; (void)out_size;
    const float* x     = (const float*)d_in[0];
    const float* A     = (const float*)d_in[1];
    const float* w1    = (const float*)d_in[2];
    const float* b1    = (const float*)d_in[3];
    const float* w2    = (const float*)d_in[4];
    const float* b2    = (const float*)d_in[5];
    const float* w3    = (const float*)d_in[6];
    const float* b3    = (const float*)d_in[7];
    const float* w4    = (const float*)d_in[8];
    const float* b4    = (const float*)d_in[9];
    const float* alpha = (const float*)d_in[10];
    const float* gamma = (const float*)d_in[11];
    const float* beta  = (const float*)d_in[12];
    float* out = (float*)d_out;

    static const int smem_bytes = SMEM_FLOATS * (int)sizeof(float);
    cudaFuncSetAttribute(k_main, cudaFuncAttributeMaxDynamicSharedMemorySize, smem_bytes);

    k_xm   <<< (NN*CC*VV + 255)/256, 256 >>>(x);
    k_w3t  <<< (SS*CC*OO + 255)/256, 256 >>>(w3);
    k_att  <<< NN*SS, 256 >>>(w1, b1, w2, b2, w4, b4, alpha, A);
    k_ybias<<< NN, 256 >>>(b3);
    k_main <<< NN*NTB, 512, smem_bytes >>>(x);
    k_bnp  <<< 1, 64 >>>(gamma, beta);
    k_final<<< 2048, 256 >>>(x, out);
}

// round 3
// speedup vs baseline: 1.7367x; 1.7367x over previous
#include <cuda_runtime.h>

#define NN 32
#define CC 64
#define OO 64
#define TT 512
#define VV 25
#define SS 3
#define RR 32
#define EPSV 1e-5f
#define TB 8            // t-tile per block
#define NTB (TT/TB)     // 64
#define TVW (TB*VV)     // 200
#define UPAD 28         // att u-row pad (float4 aligned)
#define AOS (VV*UPAD)   // 700 floats per (n,s,o)
#define VTS 10          // vT row stride: [v][t], stride 10

// ---- scratch ----
__device__ __align__(16) float g_xm[NN*CC*VV];
__device__ __align__(16) float g_att[NN*SS*OO*AOS];   // transposed [v][u], pads stay 0
__device__ __align__(16) float g_ybias[NN*OO*VV];
__device__ __align__(16) float g_w3t[SS*CC*OO];       // [s][c][o]
__device__ __align__(16) float g_y[NN*OO*TT*VV];
__device__ float g_sum[OO], g_sumsq[OO], g_scale[OO], g_shift[OO];

// ---- f32x2 helpers ----
typedef unsigned long long ull;
__device__ __forceinline__ ull pk2(float a, float b) {
    ull r; asm("mov.b64 %0, {%1, %2};" : "=l"(r) : "f"(a), "f"(b)); return r;
}
__device__ __forceinline__ void upk2(ull p, float& a, float& b) {
    asm("mov.b64 {%0, %1}, %2;" : "=f"(a), "=f"(b) : "l"(p));
}
__device__ __forceinline__ ull fma2(ull a, ull b, ull c) {
    ull d; asm("fma.rn.f32x2 %0, %1, %2, %3;" : "=l"(d) : "l"(a), "l"(b), "l"(c)); return d;
}

// ---------------------------------------------------------------------------
// Kernel 1: xm mean over T; also transposes w3 (folded to keep 6 launches)
// ---------------------------------------------------------------------------
__global__ void k_xm(const float* __restrict__ x, const float* __restrict__ w3) {
    int idx = blockIdx.x * blockDim.x + threadIdx.x;
    if (idx < SS*CC*OO) {
        int o = idx % OO, c = (idx / OO) % CC, s = idx / (OO*CC);
        g_w3t[idx] = w3[(s*OO + o)*CC + c];
    }
    if (idx >= NN*CC*VV) return;
    int v  = idx % VV;
    int nc = idx / VV;
    const float* p = x + (size_t)nc * (TT*VV) + v;
    float a0=0.f, a1=0.f, a2=0.f, a3=0.f;
    #pragma unroll 4
    for (int t = 0; t < TT; t += 4) {
        a0 += p[(t+0)*VV]; a1 += p[(t+1)*VV];
        a2 += p[(t+2)*VV]; a3 += p[(t+3)*VV];
    }
    g_xm[idx] = (a0+a1+a2+a3) * (1.0f/(float)TT);
}

// ---------------------------------------------------------------------------
// Kernel 2: attention tensor, written TRANSPOSED+PADDED: g_att[(nso)][v*28+u]
// ---------------------------------------------------------------------------
__global__ void k_att(const float* __restrict__ w1, const float* __restrict__ b1,
                      const float* __restrict__ w2, const float* __restrict__ b2,
                      const float* __restrict__ w4, const float* __restrict__ b4,
                      const float* __restrict__ alpha, const float* __restrict__ A) {
    int n = blockIdx.x / SS, s = blockIdx.x % SS;
    __shared__ float xm_sm[CC*VV];
    __shared__ float q_sm[RR*VV];
    __shared__ float k_sm[RR*VV];
    __shared__ float w4_sm[OO*RR];
    __shared__ float b4_sm[OO];
    int tid = threadIdx.x;

    for (int i = tid; i < CC*VV; i += blockDim.x) xm_sm[i] = g_xm[n*CC*VV + i];
    for (int i = tid; i < OO*RR; i += blockDim.x) w4_sm[i] = w4[s*OO*RR + i];
    if (tid < OO) b4_sm[tid] = b4[s*OO + tid];
    __syncthreads();

    for (int e = tid; e < RR*VV; e += blockDim.x) {
        int r = e / VV, v = e % VV;
        const float* w1r = w1 + (s*RR + r)*CC;
        const float* w2r = w2 + (s*RR + r)*CC;
        float accq = b1[s*RR + r], acck = b2[s*RR + r];
        #pragma unroll 8
        for (int c = 0; c < CC; c++) {
            float xv = xm_sm[c*VV + v];
            accq = fmaf(w1r[c], xv, accq);
            acck = fmaf(w2r[c], xv, acck);
        }
        q_sm[e] = accq; k_sm[e] = acck;
    }
    __syncthreads();

    float al = alpha[s];
    for (int uv = tid; uv < VV*VV; uv += blockDim.x) {
        int u = uv / VV, v = uv % VV;
        float rel[RR];
        #pragma unroll
        for (int r = 0; r < RR; r++)
            rel[r] = fmaxf(q_sm[r*VV + u] - k_sm[r*VV + v], 0.f);
        float Auv = A[(s*VV + u)*VV + v];
        float* outp = g_att + (size_t)((n*SS + s)*OO) * AOS + v*UPAD + u;
        for (int o = 0; o < OO; o++) {
            float acc = 0.f;
            #pragma unroll
            for (int r = 0; r < RR; r++)
                acc = fmaf(w4_sm[o*RR + r], rel[r], acc);
            outp[o*AOS] = al*(acc + b4_sm[o]) + Auv;
        }
    }
}

// ---------------------------------------------------------------------------
// Kernel 3: ybias + zero BN stats (reads transposed att)
// ---------------------------------------------------------------------------
__global__ void k_ybias(const float* __restrict__ b3) {
    int n = blockIdx.x;
    int tid = threadIdx.x;
    if (n == 0) {
        if (tid < OO)             g_sum[tid] = 0.f;
        else if (tid < 2*OO)      g_sumsq[tid - OO] = 0.f;
    }
    for (int e = tid; e < OO*VV; e += blockDim.x) {
        int o = e / VV, u = e % VV;
        float acc = 0.f;
        #pragma unroll
        for (int s = 0; s < SS; s++) {
            const float* ap = g_att + (size_t)((n*SS + s)*OO + o) * AOS + u;
            float rs = 0.f;
            #pragma unroll
            for (int v = 0; v < VV; v++) rs += ap[v*UPAD];
            acc = fmaf(b3[s*OO + o], rs, acc);
        }
        g_ybias[n*OO*VV + e] = acc;
    }
}

// ---------------------------------------------------------------------------
// Kernel 4 (main): fused v=w3@x, y+=att@v. 512 threads = 16 warps.
// Warp w owns o-quad [4w,4w+4). v-stage: f32x2 over tv-pairs. v stored in
// per-warp vT[oq][v][t] (stride 10). y-stage: per v, 1 LDG.128 att (conflict-
// free, u contiguous) + 1 LDS.64 t-pair + 4 f32x2 FMA. No block syncs in loop.
// ---------------------------------------------------------------------------
#define SM_XS (CC*TVW)        // 12800
#define SM_VT (16*4*VV*VTS)   // 16000
#define SMEM_FLOATS (SM_XS + SM_VT)   // 28800 floats = 115,200 B

__global__ void __launch_bounds__(512)
k_main(const float* __restrict__ x) {
    extern __shared__ float sm[];
    float* xs = sm;
    float* vt = sm + SM_XS;

    int n  = blockIdx.x / NTB;
    int tb = blockIdx.x % NTB;
    int t0 = tb * TB;
    int tid = threadIdx.x, w = tid >> 5, lane = tid & 31;

    // stage x tile [c][200]
    float4* xs4 = (float4*)xs;
    for (int i = tid; i < CC*50; i += 512) {
        int c = i / 50, qd = i % 50;
        xs4[c*50 + qd] = *(const float4*)(x + (size_t)(n*CC + c)*(TT*VV) + t0*VV + qd*4);
    }

    int tp = lane >> 3, ug = lane & 7;

    // dump coords for pairs tv=2*(lane+32j), tv+1
    int dv0[3], dt0[3], dv1[3], dt1[3];
    #pragma unroll
    for (int j = 0; j < 3; j++) {
        int tv0 = 2*(lane + 32*j);
        dt0[j] = tv0 / VV; dv0[j] = tv0 % VV;
        int tv1 = tv0 + 1;
        dt1[j] = tv1 / VV; dv1[j] = tv1 % VV;
    }
    int tvt = (192 + lane) / VV, tvv = (192 + lane) % VV;   // tail (lanes<8)

    // persistent acc: acc2[oq][t(local pair)][u-pair], f32x2 packed
    ull acc2[4][2][2];
    #pragma unroll
    for (int oq = 0; oq < 4; oq++) {
        const float* yb = g_ybias + (size_t)(n*OO + 4*w + oq)*VV;
        #pragma unroll
        for (int p = 0; p < 2; p++) {
            int u0 = 4*ug + 2*p;
            float y0 = (u0   < VV) ? yb[u0]   : 0.f;
            float y1 = (u0+1 < VV) ? yb[u0+1] : 0.f;
            ull ybp = pk2(y0, y1);
            acc2[oq][0][p] = ybp; acc2[oq][1][p] = ybp;
        }
    }
    __syncthreads();

    float* vtw = vt + w * (4*VV*VTS);

    for (int s = 0; s < SS; s++) {
        // ---- v-stage ----
        ull accp[4][3];
        float acct[4];
        #pragma unroll
        for (int oq = 0; oq < 4; oq++) {
            acct[oq] = 0.f;
            #pragma unroll
            for (int j = 0; j < 3; j++) accp[oq][j] = 0ull;
        }
        const float* wrow = g_w3t + (size_t)(s*CC)*OO + 4*w;
        #pragma unroll 4
        for (int c = 0; c < CC; c++) {
            float4 wq = *(const float4*)(wrow + c*OO);
            ull ws0 = pk2(wq.x, wq.x), ws1 = pk2(wq.y, wq.y);
            ull ws2 = pk2(wq.z, wq.z), ws3 = pk2(wq.w, wq.w);
            const float* xr = xs + c*TVW;
            ull xp0 = *(const ull*)(xr + 2*lane);
            ull xp1 = *(const ull*)(xr + 2*lane + 64);
            ull xp2 = *(const ull*)(xr + 2*lane + 128);
            accp[0][0]=fma2(ws0,xp0,accp[0][0]); accp[0][1]=fma2(ws0,xp1,accp[0][1]); accp[0][2]=fma2(ws0,xp2,accp[0][2]);
            accp[1][0]=fma2(ws1,xp0,accp[1][0]); accp[1][1]=fma2(ws1,xp1,accp[1][1]); accp[1][2]=fma2(ws1,xp2,accp[1][2]);
            accp[2][0]=fma2(ws2,xp0,accp[2][0]); accp[2][1]=fma2(ws2,xp1,accp[2][1]); accp[2][2]=fma2(ws2,xp2,accp[2][2]);
            accp[3][0]=fma2(ws3,xp0,accp[3][0]); accp[3][1]=fma2(ws3,xp1,accp[3][1]); accp[3][2]=fma2(ws3,xp2,accp[3][2]);
            float xt = (lane < 8) ? xr[192 + lane] : 0.f;
            acct[0] = fmaf(wq.x, xt, acct[0]);
            acct[1] = fmaf(wq.y, xt, acct[1]);
            acct[2] = fmaf(wq.z, xt, acct[2]);
            acct[3] = fmaf(wq.w, xt, acct[3]);
        }

        __syncwarp();   // prior y-stage reads of vtw done
        // ---- dump vT[oq][v][t] ----
        #pragma unroll
        for (int oq = 0; oq < 4; oq++) {
            float* d = vtw + oq*(VV*VTS);
            #pragma unroll
            for (int j = 0; j < 3; j++) {
                float lo, hi; upk2(accp[oq][j], lo, hi);
                d[dv0[j]*VTS + dt0[j]] = lo;
                d[dv1[j]*VTS + dt1[j]] = hi;
            }
            if (lane < 8) d[tvv*VTS + tvt] = acct[oq];
        }
        __syncwarp();

        // ---- y-stage ----
        #pragma unroll
        for (int oq = 0; oq < 4; oq++) {
            const float* dv = vtw + oq*(VV*VTS) + 2*tp;
            const float* ag = g_att + (size_t)((n*SS + s)*OO + 4*w + oq)*AOS + 4*ug;
            #pragma unroll
            for (int v = 0; v < VV; v++) {
                float2 vab = *(const float2*)(dv + v*VTS);
                ull vaa = pk2(vab.x, vab.x);
                ull vbb = pk2(vab.y, vab.y);
                ulonglong2 at = *(const ulonglong2*)(ag + v*UPAD);
                acc2[oq][0][0] = fma2(at.x, vaa, acc2[oq][0][0]);
                acc2[oq][0][1] = fma2(at.y, vaa, acc2[oq][0][1]);
                acc2[oq][1][0] = fma2(at.x, vbb, acc2[oq][1][0]);
                acc2[oq][1][1] = fma2(at.y, vbb, acc2[oq][1][1]);
            }
        }
    }

    // ---- epilogue ----
    #pragma unroll
    for (int oq = 0; oq < 4; oq++) {
        int o = 4*w + oq;
        float ps = 0.f, pss = 0.f;
        #pragma unroll
        for (int j = 0; j < 2; j++) {
            int t = 2*tp + j;
            float uv0, uv1, uv2, uv3;
            upk2(acc2[oq][j][0], uv0, uv1);
            upk2(acc2[oq][j][1], uv2, uv3);
            float vals[4] = {uv0, uv1, uv2, uv3};
            float* yp = g_y + ((size_t)(n*OO + o)*TT + t0 + t)*VV;
            #pragma unroll
            for (int i = 0; i < 4; i++) {
                int u = 4*ug + i;
                if (u < VV) {
                    yp[u] = vals[i];
                    ps  += vals[i];
                    pss += vals[i]*vals[i];
                }
            }
        }
        #pragma unroll
        for (int off = 16; off > 0; off >>= 1) {
            ps  += __shfl_xor_sync(0xffffffffu, ps,  off);
            pss += __shfl_xor_sync(0xffffffffu, pss, off);
        }
        if (lane == 0) {
            atomicAdd(&g_sum[o],   ps);
            atomicAdd(&g_sumsq[o], pss);
        }
    }
}

// ---------------------------------------------------------------------------
// Kernel 5: BN scale/shift
// ---------------------------------------------------------------------------
__global__ void k_bnp(const float* __restrict__ gamma, const float* __restrict__ beta) {
    int o = threadIdx.x;
    if (o < OO) {
        float cnt = (float)(NN*TT*VV);
        float mu  = g_sum[o] / cnt;
        float var = g_sumsq[o] / cnt - mu*mu;
        float sc  = gamma[o] * rsqrtf(var + EPSV);
        g_scale[o] = sc;
        g_shift[o] = beta[o] - mu*sc;
    }
}

// ---------------------------------------------------------------------------
// Kernel 6: out = relu(y) + y*scale + shift + x
// ---------------------------------------------------------------------------
__global__ void k_final(const float* __restrict__ x, float* __restrict__ out) {
    const int total4 = NN*OO*TT*VV / 4;
    for (int i = blockIdx.x*blockDim.x + threadIdx.x; i < total4; i += gridDim.x*blockDim.x) {
        int c = (i / (TT*VV/4)) % OO;
        float sc = g_scale[c], sh = g_shift[c];
        float4 y4 = ((const float4*)g_y)[i];
        float4 x4 = ((const float4*)x)[i];
        float4 r;
        r.x = fmaxf(y4.x, 0.f) + fmaf(y4.x, sc, sh) + x4.x;
        r.y = fmaxf(y4.y, 0.f) + fmaf(y4.y, sc, sh) + x4.y;
        r.z = fmaxf(y4.z, 0.f) + fmaf(y4.z, sc, sh) + x4.z;
        r.w = fmaxf(y4.w, 0.f) + fmaf(y4.w, sc, sh) + x4.w;
        ((float4*)out)[i] = r;
    }
}

// ---------------------------------------------------------------------------
extern "C" void kernel_launch(void* const* d_in, const int* in_sizes, int n_in,
                              void* d_out, int out_size) {
    (void)in_sizes; (void)n_in; (void)out_size;
    const float* x     = (const float*)d_in[0];
    const float* A     = (const float*)d_in[1];
    const float* w1    = (const float*)d_in[2];
    const float* b1    = (const float*)d_in[3];
    const float* w2    = (const float*)d_in[4];
    const float* b2    = (const float*)d_in[5];
    const float* w3    = (const float*)d_in[6];
    const float* b3    = (const float*)d_in[7];
    const float* w4    = (const float*)d_in[8];
    const float* b4    = (const float*)d_in[9];
    const float* alpha = (const float*)d_in[10];
    const float* gamma = (const float*)d_in[11];
    const float* beta  = (const float*)d_in[12];
    float* out = (float*)d_out;

    static const int smem_bytes = SMEM_FLOATS * (int)sizeof(float);
    cudaFuncSetAttribute(k_main, cudaFuncAttributeMaxDynamicSharedMemorySize, smem_bytes);

    k_xm   <<< (NN*CC*VV + 255)/256, 256 >>>(x, w3);
    k_att  <<< NN*SS, 256 >>>(w1, b1, w2, b2, w4, b4, alpha, A);
    k_ybias<<< NN, 256 >>>(b3);
    k_main <<< NN*NTB, 512, smem_bytes >>>(x);
    k_bnp  <<< 1, 64 >>>(gamma, beta);
    k_final<<< 2048, 256 >>>(x, out);
}